// round 1
// baseline (speedup 1.0000x reference)
#include <cuda_runtime.h>
#include <math.h>

#define TT 64
#define DIMM 2048
#define SLOTSS 256

// -------- device scratch (no allocations allowed) --------
__device__ float g_noisy[TT * DIMM];
__device__ float g_h[TT * DIMM];
__device__ float g_x[TT * DIMM];
__device__ float g_lv[TT * DIMM];
__device__ float g_gated[TT * DIMM];
__device__ float g_er[TT * DIMM];
__device__ float g_ad[TT * DIMM];
__device__ float g_lpart[8 * TT * SLOTSS];
__device__ float g_c[TT * SLOTSS];

__device__ __forceinline__ float sigmoidf_(float v) { return 1.f / (1.f + expf(-v)); }

enum { M_RELU = 0, M_ID, M_LIG, M_GATE, M_SIG, M_PART };

// ---------------------------------------------------------------------------
// prep: noisy[t][d] = traces[idx[t]][d] + 0.01 * noise[t][d]
// ---------------------------------------------------------------------------
__global__ void prep_kernel(const float* __restrict__ traces,
                            const float* __restrict__ noise,
                            const int* __restrict__ idx,
                            float* __restrict__ noisy) {
    int t = blockIdx.y;
    int d = (blockIdx.x * 256 + threadIdx.x) * 4;
    int row = idx[t];
    float4 tr = *(const float4*)&traces[(size_t)row * DIMM + d];
    float4 nz = *(const float4*)&noise[(size_t)t * DIMM + d];
    float4 o;
    o.x = tr.x + 0.01f * nz.x;
    o.y = tr.y + 0.01f * nz.y;
    o.z = tr.z + 0.01f * nz.z;
    o.w = tr.w + 0.01f * nz.w;
    *(float4*)&noisy[(size_t)t * DIMM + d] = o;
}

// ---------------------------------------------------------------------------
// GEMM: out[t][i] = epilogue( sum_k A[t][k]*W[i][k] + bias[i] )
// A: (64 x 2048) row-major, W: (I_total x 2048) row-major.
// Tiling: BT=64, BI=16, BK=32. 256 threads, thread tile 4t x 1i.
// Smem tiles stored k-major (transposed) with pad; double buffered.
// grid = (I_total/16, ksplit), Kper = 2048/ksplit.
// ---------------------------------------------------------------------------
template <int MODE>
__global__ __launch_bounds__(256) void gemm_kernel(
    const float* __restrict__ A, const float* __restrict__ W,
    const float* __restrict__ bias, float* __restrict__ out,
    const float* __restrict__ xbuf, const float* __restrict__ vw,
    const float* __restrict__ vb, int I_total, int Kper) {
    __shared__ __align__(16) float As[2][32][68];  // [buf][k][t], pad 68
    __shared__ float Ws[2][32][17];                // [buf][k][i], pad 17

    const int tid = threadIdx.x;
    const int I0 = blockIdx.x * 16;
    const int kb = blockIdx.y * Kper;

    // global-load mappings
    const int a_t = tid >> 2;              // 0..63
    const int a_k = (tid & 3) * 8;         // 0,8,16,24 (two float4s)
    const float* Ag = A + (size_t)a_t * DIMM + kb + a_k;
    const int w_i = tid >> 3;              // 0..31 (valid < 16 rows when tid<128)
    const int w_k = (tid & 7) * 4;
    const float* Wgp = W + (size_t)(I0 + (w_i & 15)) * DIMM + kb + w_k;

    // compute mapping: warp = 4 i x 8 t-groups
    const int lane = tid & 31, wrp = tid >> 5;
    const int i_loc = ((wrp & 3) << 2) + (lane & 3);                 // 0..15
    const int t_loc = ((((wrp >> 2) << 3) + (lane >> 2)) << 2);      // 0..60 step 4

    float4 ar0, ar1, wr;
    // prologue: tile 0 -> buf 0
    ar0 = *(const float4*)(Ag);
    ar1 = *(const float4*)(Ag + 4);
    if (tid < 128) wr = *(const float4*)(Wgp);
    As[0][a_k + 0][a_t] = ar0.x; As[0][a_k + 1][a_t] = ar0.y;
    As[0][a_k + 2][a_t] = ar0.z; As[0][a_k + 3][a_t] = ar0.w;
    As[0][a_k + 4][a_t] = ar1.x; As[0][a_k + 5][a_t] = ar1.y;
    As[0][a_k + 6][a_t] = ar1.z; As[0][a_k + 7][a_t] = ar1.w;
    if (tid < 128) {
        Ws[0][w_k + 0][w_i] = wr.x; Ws[0][w_k + 1][w_i] = wr.y;
        Ws[0][w_k + 2][w_i] = wr.z; Ws[0][w_k + 3][w_i] = wr.w;
    }
    __syncthreads();

    float acc0 = 0.f, acc1 = 0.f, acc2 = 0.f, acc3 = 0.f;
    const int nk = Kper >> 5;
    for (int kt = 0; kt < nk; kt++) {
        const int cur = kt & 1;
        if (kt + 1 < nk) {
            const float* Ap = Ag + (kt + 1) * 32;
            ar0 = *(const float4*)(Ap);
            ar1 = *(const float4*)(Ap + 4);
            if (tid < 128) wr = *(const float4*)(Wgp + (kt + 1) * 32);
        }
#pragma unroll
        for (int kk = 0; kk < 32; kk++) {
            float4 av = *(const float4*)(&As[cur][kk][t_loc]);
            float wv = Ws[cur][kk][i_loc];
            acc0 = fmaf(av.x, wv, acc0);
            acc1 = fmaf(av.y, wv, acc1);
            acc2 = fmaf(av.z, wv, acc2);
            acc3 = fmaf(av.w, wv, acc3);
        }
        if (kt + 1 < nk) {
            const int nxt = cur ^ 1;
            As[nxt][a_k + 0][a_t] = ar0.x; As[nxt][a_k + 1][a_t] = ar0.y;
            As[nxt][a_k + 2][a_t] = ar0.z; As[nxt][a_k + 3][a_t] = ar0.w;
            As[nxt][a_k + 4][a_t] = ar1.x; As[nxt][a_k + 5][a_t] = ar1.y;
            As[nxt][a_k + 6][a_t] = ar1.z; As[nxt][a_k + 7][a_t] = ar1.w;
            if (tid < 128) {
                Ws[nxt][w_k + 0][w_i] = wr.x; Ws[nxt][w_k + 1][w_i] = wr.y;
                Ws[nxt][w_k + 2][w_i] = wr.z; Ws[nxt][w_k + 3][w_i] = wr.w;
            }
        }
        __syncthreads();
    }

    // epilogue
    const int iglob = I0 + i_loc;
    const float b = (MODE == M_PART) ? 0.f : bias[iglob];
    float accs[4] = {acc0, acc1, acc2, acc3};
#pragma unroll
    for (int j = 0; j < 4; j++) {
        const int t = t_loc + j;
        const float v = accs[j] + b;
        float r;
        if (MODE == M_RELU) {
            r = v > 0.f ? v : 0.f;
        } else if (MODE == M_ID) {
            r = v;
        } else if (MODE == M_SIG) {
            r = sigmoidf_(v);
        } else if (MODE == M_LIG) {
            // phase = mod(2*pi*6*0.01*(t+1), 2*pi); signal = cos(phase - pi) = -cos(phase)
            float ang = fmodf(0.37699111843077515f * (float)(t + 1), 6.2831853071795865f);
            float ps = -cosf(ang);
            float volt = sigmoidf_(fmaf(ps, vw[iglob], vb[iglob]));
            r = sigmoidf_(v) * volt;
        } else if (MODE == M_GATE) {
            r = xbuf[(size_t)t * DIMM + iglob] * sigmoidf_(v);
        } else {  // M_PART
            r = v;
        }
        if (MODE == M_PART)
            out[(size_t)blockIdx.y * TT * SLOTSS + (size_t)t * SLOTSS + iglob] = r;
        else
            out[(size_t)t * I_total + iglob] = r;
    }
}

// ---------------------------------------------------------------------------
// sequential softmax chain: c[t][s] = 0.5 * softmax_s(logits[t] - 0.1*usage),
// usage += softmax.  One block of 256 threads (one per slot).
// logits summed from 8 K-split partials + bias.
// ---------------------------------------------------------------------------
__global__ __launch_bounds__(256) void softmax_chain(
    const float* __restrict__ lpart, const float* __restrict__ ba,
    float* __restrict__ cbuf) {
    const int s = threadIdx.x, lane = s & 31, wid = s >> 5;
    __shared__ float redm[8], reds[8];
    __shared__ float bmax, bsum;
    float usage = 0.f;
    const float base = ba[s];
    for (int t = 0; t < TT; t++) {
        float lg = base;
#pragma unroll
        for (int ks = 0; ks < 8; ks++) lg += lpart[((size_t)ks * TT + t) * SLOTSS + s];
        const float v = fmaf(-0.1f, usage, lg);
        float m = v;
#pragma unroll
        for (int o = 16; o > 0; o >>= 1) m = fmaxf(m, __shfl_xor_sync(0xffffffffu, m, o));
        if (lane == 0) redm[wid] = m;
        __syncthreads();
        if (s == 0) {
            float mm = redm[0];
#pragma unroll
            for (int i = 1; i < 8; i++) mm = fmaxf(mm, redm[i]);
            bmax = mm;
        }
        __syncthreads();
        const float e = expf(v - bmax);
        float su = e;
#pragma unroll
        for (int o = 16; o > 0; o >>= 1) su += __shfl_xor_sync(0xffffffffu, su, o);
        if (lane == 0) reds[wid] = su;
        __syncthreads();
        if (s == 0) {
            float ss = 0.f;
#pragma unroll
            for (int i = 0; i < 8; i++) ss += reds[i];
            bsum = ss;
        }
        __syncthreads();
        const float wgt = e / bsum;
        cbuf[t * SLOTSS + s] = 0.5f * wgt;
        usage += wgt;
        __syncthreads();
    }
}

// ---------------------------------------------------------------------------
// memory update: per (s,d) run the T=64 recurrence
//   m = m*(1 - c[t][s]*er[t][d]) + c[t][s]*ad[t][d]
// Block tile: 64 slots x 64 dims, thread tile 4x4. Grid = 4 x 32 = 128 blocks.
// ---------------------------------------------------------------------------
__global__ __launch_bounds__(256) void memupd_kernel(
    const float* __restrict__ cbuf, const float* __restrict__ er,
    const float* __restrict__ ad, const float* __restrict__ mem0,
    float* __restrict__ out) {
    __shared__ __align__(16) float cs[64][64];
    __shared__ __align__(16) float es[64][64];
    __shared__ __align__(16) float ds[64][64];
    const int tid = threadIdx.x;
    const int S0 = (blockIdx.x & 3) * 64;
    const int D0 = (blockIdx.x >> 2) * 64;
#pragma unroll
    for (int j = 0; j < 4; j++) {
        int f = tid + j * 256;
        int t = f >> 4, q = (f & 15) * 4;
        *(float4*)&cs[t][q] = *(const float4*)&cbuf[(size_t)t * SLOTSS + S0 + q];
        *(float4*)&es[t][q] = *(const float4*)&er[(size_t)t * DIMM + D0 + q];
        *(float4*)&ds[t][q] = *(const float4*)&ad[(size_t)t * DIMM + D0 + q];
    }
    __syncthreads();
    const int sg = (tid >> 4) * 4, dg = (tid & 15) * 4;
    float m[4][4];
#pragma unroll
    for (int j = 0; j < 4; j++)
        *(float4*)m[j] = *(const float4*)&mem0[(size_t)(S0 + sg + j) * DIMM + D0 + dg];
    for (int t = 0; t < 64; t++) {
        float4 c4 = *(const float4*)&cs[t][sg];
        float4 e4 = *(const float4*)&es[t][dg];
        float4 a4 = *(const float4*)&ds[t][dg];
        float c[4] = {c4.x, c4.y, c4.z, c4.w};
        float e[4] = {e4.x, e4.y, e4.z, e4.w};
        float a[4] = {a4.x, a4.y, a4.z, a4.w};
#pragma unroll
        for (int j = 0; j < 4; j++)
#pragma unroll
            for (int l = 0; l < 4; l++)
                m[j][l] = fmaf(c[j], fmaf(-e[l], m[j][l], a[l]), m[j][l]);
    }
#pragma unroll
    for (int j = 0; j < 4; j++)
        *(float4*)&out[(size_t)(S0 + sg + j) * DIMM + D0 + dg] = *(float4*)m[j];
}

// ---------------------------------------------------------------------------
// launch
// ---------------------------------------------------------------------------
extern "C" void kernel_launch(void* const* d_in, const int* in_sizes, int n_in,
                              void* d_out, int out_size) {
    const float* traces = (const float*)d_in[0];
    const float* noise  = (const float*)d_in[1];
    const float* mem0   = (const float*)d_in[2];
    // d_in[3] = usage0 (zeros; usage starts at 0 in the chain kernel)
    const float* W1 = (const float*)d_in[4];
    const float* b1 = (const float*)d_in[5];
    const float* W2 = (const float*)d_in[6];
    const float* b2 = (const float*)d_in[7];
    const float* Wl = (const float*)d_in[8];
    const float* bl = (const float*)d_in[9];
    const float* vw = (const float*)d_in[10];
    const float* vb = (const float*)d_in[11];
    const float* Wg = (const float*)d_in[12];
    const float* bg = (const float*)d_in[13];
    const float* Wa = (const float*)d_in[14];
    const float* ba = (const float*)d_in[15];
    const float* We = (const float*)d_in[16];
    const float* be = (const float*)d_in[17];
    const float* Wad = (const float*)d_in[18];
    const float* bad = (const float*)d_in[19];
    const int* idx = (const int*)d_in[20];
    float* out = (float*)d_out;

    float *noisy, *h, *x, *lv, *gated, *er, *ad, *lpart, *cbuf;
    cudaGetSymbolAddress((void**)&noisy, g_noisy);
    cudaGetSymbolAddress((void**)&h, g_h);
    cudaGetSymbolAddress((void**)&x, g_x);
    cudaGetSymbolAddress((void**)&lv, g_lv);
    cudaGetSymbolAddress((void**)&gated, g_gated);
    cudaGetSymbolAddress((void**)&er, g_er);
    cudaGetSymbolAddress((void**)&ad, g_ad);
    cudaGetSymbolAddress((void**)&lpart, g_lpart);
    cudaGetSymbolAddress((void**)&cbuf, g_c);

    prep_kernel<<<dim3(2, TT), 256>>>(traces, noise, idx, noisy);

    dim3 gbig(DIMM / 16, 1);
    gemm_kernel<M_RELU><<<gbig, 256>>>(noisy, W1, b1, h, nullptr, nullptr, nullptr, DIMM, DIMM);
    gemm_kernel<M_ID>  <<<gbig, 256>>>(h, W2, b2, x, nullptr, nullptr, nullptr, DIMM, DIMM);
    gemm_kernel<M_LIG> <<<gbig, 256>>>(x, Wl, bl, lv, nullptr, vw, vb, DIMM, DIMM);
    gemm_kernel<M_GATE><<<gbig, 256>>>(lv, Wg, bg, gated, x, nullptr, nullptr, DIMM, DIMM);
    gemm_kernel<M_SIG> <<<gbig, 256>>>(gated, We, be, er, nullptr, nullptr, nullptr, DIMM, DIMM);
    gemm_kernel<M_ID>  <<<gbig, 256>>>(gated, Wad, bad, ad, nullptr, nullptr, nullptr, DIMM, DIMM);
    gemm_kernel<M_PART><<<dim3(SLOTSS / 16, 8), 256>>>(gated, Wa, nullptr, lpart,
                                                       nullptr, nullptr, nullptr, SLOTSS, DIMM / 8);

    softmax_chain<<<1, 256>>>(lpart, ba, cbuf);
    memupd_kernel<<<128, 256>>>(cbuf, er, ad, mem0, out);
}

// round 2
// speedup vs baseline: 2.4333x; 2.4333x over previous
#include <cuda_runtime.h>
#include <cuda_bf16.h>
#include <math.h>
#include <stdint.h>

#define TT 64
#define DIMM 2048
#define SLOTSS 256
#define KS 8
#define KPER (DIMM / KS)    // 256
#define NCHUNK (KPER / 16)  // 16 chunks of 16 original-k each
#define SPAD 40             // smem row stride (elems): 32 data + 8 pad -> conflict-free ldmatrix

// -------- device scratch (no allocations allowed) --------
__device__ float g_noisy[TT * DIMM];
__device__ float g_h[TT * DIMM];
__device__ float g_x[TT * DIMM];
__device__ float g_lv[TT * DIMM];
__device__ float g_gated[TT * DIMM];
__device__ float g_er[TT * DIMM];
__device__ float g_ad[TT * DIMM];
__device__ float g_part[KS * TT * DIMM];   // k-split partials (4 MB)
__device__ float g_lg[TT * SLOTSS];        // logits (bias added)
__device__ float g_c[TT * SLOTSS];         // 0.5 * softmax weights

__device__ __forceinline__ float sigmoidf_(float v) { return 1.f / (1.f + expf(-v)); }

enum { M_RELU = 0, M_ID, M_LIG, M_GATE, M_SIG };

// ---------------------------------------------------------------------------
// prep: noisy[t][d] = traces[idx[t]][d] + 0.01 * noise[t][d]
// ---------------------------------------------------------------------------
__global__ void prep_kernel(const float* __restrict__ traces,
                            const float* __restrict__ noise,
                            const int* __restrict__ idx,
                            float* __restrict__ noisy) {
    int t = blockIdx.y;
    int d = (blockIdx.x * 256 + threadIdx.x) * 4;
    int row = idx[t];
    float4 tr = *(const float4*)&traces[(size_t)row * DIMM + d];
    float4 nz = *(const float4*)&noise[(size_t)t * DIMM + d];
    float4 o;
    o.x = tr.x + 0.01f * nz.x;
    o.y = tr.y + 0.01f * nz.y;
    o.z = tr.z + 0.01f * nz.z;
    o.w = tr.w + 0.01f * nz.w;
    *(float4*)&noisy[(size_t)t * DIMM + d] = o;
}

// ---------------------------------------------------------------------------
// Tensor-core GEMM partial: part[ks][t][n] = sum_{k in slab} A[t][k]*W[n][k]
// fp32 emulated via bf16 hi/lo split: Ahi*Whi + Ahi*Wlo + Alo*Whi.
// Block: M=64 x N=128, K-slab=256 (KS=8 split), 256 threads (8 warps, 32x32
// warp tiles). Smem staging converts fp32 -> hi/lo bf16 once per block.
// grid = (Ntot/128, KS)
// ---------------------------------------------------------------------------
__device__ __forceinline__ void ldsm4(uint32_t* r, uint32_t addr) {
    asm volatile("ldmatrix.sync.aligned.m8n8.x4.shared.b16 {%0,%1,%2,%3}, [%4];"
                 : "=r"(r[0]), "=r"(r[1]), "=r"(r[2]), "=r"(r[3]) : "r"(addr));
}
__device__ __forceinline__ void mma16816(float* d, const uint32_t* a, uint32_t b0, uint32_t b1) {
    asm volatile(
        "mma.sync.aligned.m16n8k16.row.col.f32.bf16.bf16.f32 "
        "{%0,%1,%2,%3}, {%4,%5,%6,%7}, {%8,%9}, {%0,%1,%2,%3};"
        : "+f"(d[0]), "+f"(d[1]), "+f"(d[2]), "+f"(d[3])
        : "r"(a[0]), "r"(a[1]), "r"(a[2]), "r"(a[3]), "r"(b0), "r"(b1));
}

__global__ __launch_bounds__(256) void gemm_mma(
    const float* __restrict__ A, const float* __restrict__ W,
    float* __restrict__ part, int Ntot) {
    __shared__ __nv_bfloat16 As[2][64][SPAD];   // cols: [0..15]=hi, [16..31]=lo
    __shared__ __nv_bfloat16 Ws[2][128][SPAD];  // cols: [0..15]=hi, [16..31]=lo

    const int tid = threadIdx.x;
    const int n0 = blockIdx.x * 128;
    const int kb = blockIdx.y * KPER;

    // global load mapping: A 64x16 fp32 (1 float4/thr), W 128x16 fp32 (2 float4/thr)
    const int a_row = tid >> 2, a_kq = (tid & 3) * 4;
    const float* Ag = A + (size_t)a_row * DIMM + kb + a_kq;
    const int w_row = tid >> 1, w_kq = (tid & 1) * 8;
    const float* Wgp = W + (size_t)(n0 + w_row) * DIMM + kb + w_kq;

    // compute mapping
    const int lane = tid & 31, wid = tid >> 5;
    const int m0w = (wid >> 2) * 32;   // warp m origin (0/32)
    const int n0w = (wid & 3) * 32;    // warp n origin (0/32/64/96)
    const int g = lane >> 3, r = lane & 7;
    // A ldmatrix lane offset (elems): mats (m0,k0),(m8,k0),(m0,k8),(m8,k8)
    const int aoff = (m0w + (g & 1) * 8 + r) * SPAD + (g >> 1) * 8;
    // B ldmatrix lane offset: mats (n0,k0),(n0,k8),(n8,k0),(n8,k8)
    const int boff = (n0w + (g >> 1) * 8 + r) * SPAD + (g & 1) * 8;

    const uint32_t asbase = (uint32_t)__cvta_generic_to_shared(&As[0][0][0]);
    const uint32_t wsbase = (uint32_t)__cvta_generic_to_shared(&Ws[0][0][0]);
    const uint32_t ABUF = 64 * SPAD * 2, WBUF = 128 * SPAD * 2;

    float av[4], wv[8];
    // prologue: load chunk 0
    {
        float4 t4 = *(const float4*)(Ag);
        av[0] = t4.x; av[1] = t4.y; av[2] = t4.z; av[3] = t4.w;
        float4 u0 = *(const float4*)(Wgp);
        float4 u1 = *(const float4*)(Wgp + 4);
        wv[0] = u0.x; wv[1] = u0.y; wv[2] = u0.z; wv[3] = u0.w;
        wv[4] = u1.x; wv[5] = u1.y; wv[6] = u1.z; wv[7] = u1.w;
    }
#define CVT_STORE(buf)                                                     \
    {                                                                      \
        _Pragma("unroll") for (int i = 0; i < 4; i++) {                    \
            __nv_bfloat16 hi = __float2bfloat16(av[i]);                    \
            float rem = av[i] - __bfloat162float(hi);                      \
            As[buf][a_row][a_kq + i] = hi;                                 \
            As[buf][a_row][a_kq + i + 16] = __float2bfloat16(rem);         \
        }                                                                  \
        _Pragma("unroll") for (int i = 0; i < 8; i++) {                    \
            __nv_bfloat16 hi = __float2bfloat16(wv[i]);                    \
            float rem = wv[i] - __bfloat162float(hi);                      \
            Ws[buf][w_row][w_kq + i] = hi;                                 \
            Ws[buf][w_row][w_kq + i + 16] = __float2bfloat16(rem);         \
        }                                                                  \
    }
    CVT_STORE(0);
    __syncthreads();

    float d[2][4][4];
#pragma unroll
    for (int mt = 0; mt < 2; mt++)
#pragma unroll
        for (int nf = 0; nf < 4; nf++)
#pragma unroll
            for (int j = 0; j < 4; j++) d[mt][nf][j] = 0.f;

    for (int c = 0; c < NCHUNK; c++) {
        const int cur = c & 1;
        if (c + 1 < NCHUNK) {
            float4 t4 = *(const float4*)(Ag + (c + 1) * 16);
            av[0] = t4.x; av[1] = t4.y; av[2] = t4.z; av[3] = t4.w;
            float4 u0 = *(const float4*)(Wgp + (c + 1) * 16);
            float4 u1 = *(const float4*)(Wgp + (c + 1) * 16 + 4);
            wv[0] = u0.x; wv[1] = u0.y; wv[2] = u0.z; wv[3] = u0.w;
            wv[4] = u1.x; wv[5] = u1.y; wv[6] = u1.z; wv[7] = u1.w;
        }
        // load fragments: A hi(sec0)/lo(sec1), B hi/lo
        uint32_t a[2][2][4], b[2][2][4];
#pragma unroll
        for (int mt = 0; mt < 2; mt++)
#pragma unroll
            for (int sec = 0; sec < 2; sec++)
                ldsm4(a[mt][sec], asbase + cur * ABUF + (uint32_t)(aoff + mt * 16 * SPAD + sec * 16) * 2);
#pragma unroll
        for (int pr = 0; pr < 2; pr++)
#pragma unroll
            for (int sec = 0; sec < 2; sec++)
                ldsm4(b[pr][sec], wsbase + cur * WBUF + (uint32_t)(boff + pr * 16 * SPAD + sec * 16) * 2);
        // 3 combos: (Ahi,Whi), (Ahi,Wlo), (Alo,Whi)
#pragma unroll
        for (int q = 0; q < 3; q++) {
            const int as = (q == 2) ? 1 : 0;
            const int ws = (q == 1) ? 1 : 0;
#pragma unroll
            for (int mt = 0; mt < 2; mt++)
#pragma unroll
                for (int nf = 0; nf < 4; nf++) {
                    const int pr = nf >> 1, hl = nf & 1;
                    mma16816(d[mt][nf], a[mt][as], b[pr][ws][hl * 2], b[pr][ws][hl * 2 + 1]);
                }
        }
        if (c + 1 < NCHUNK) CVT_STORE(cur ^ 1);
        __syncthreads();
    }

    // write partials
    const int mbase = blockIdx.y * 64;
#pragma unroll
    for (int mt = 0; mt < 2; mt++)
#pragma unroll
        for (int nf = 0; nf < 4; nf++) {
            const int m = m0w + mt * 16 + (lane >> 2);
            const int n = n0 + n0w + nf * 8 + (lane & 3) * 2;
            float2 v0 = make_float2(d[mt][nf][0], d[mt][nf][1]);
            float2 v1 = make_float2(d[mt][nf][2], d[mt][nf][3]);
            *(float2*)&part[(size_t)(mbase + m) * Ntot + n] = v0;
            *(float2*)&part[(size_t)(mbase + m + 8) * Ntot + n] = v1;
        }
}
#undef CVT_STORE

// ---------------------------------------------------------------------------
// reduce k-split partials + bias + activation
// ---------------------------------------------------------------------------
template <int MODE>
__global__ __launch_bounds__(256) void reduce_epi(
    const float* __restrict__ part, const float* __restrict__ bias,
    float* __restrict__ out, const float* __restrict__ xbuf,
    const float* __restrict__ vw, const float* __restrict__ vb, int Ntot) {
    const int flat = (blockIdx.x * 256 + threadIdx.x) * 4;
    const int t = flat / Ntot;
    const int n = flat % Ntot;
    float acc[4] = {0.f, 0.f, 0.f, 0.f};
#pragma unroll
    for (int k = 0; k < KS; k++) {
        float4 p = *(const float4*)&part[(size_t)k * TT * Ntot + flat];
        acc[0] += p.x; acc[1] += p.y; acc[2] += p.z; acc[3] += p.w;
    }
    float4 b4 = *(const float4*)&bias[n];
    float bb[4] = {b4.x, b4.y, b4.z, b4.w};
    float res[4];
#pragma unroll
    for (int j = 0; j < 4; j++) {
        const float v = acc[j] + bb[j];
        if (MODE == M_RELU) {
            res[j] = v > 0.f ? v : 0.f;
        } else if (MODE == M_ID) {
            res[j] = v;
        } else if (MODE == M_SIG) {
            res[j] = sigmoidf_(v);
        } else if (MODE == M_LIG) {
            float ang = fmodf(0.37699111843077515f * (float)(t + 1), 6.2831853071795865f);
            float ps = -cosf(ang);
            float volt = sigmoidf_(fmaf(ps, vw[n + j], vb[n + j]));
            res[j] = sigmoidf_(v) * volt;
        } else {  // M_GATE
            res[j] = xbuf[flat + j] * sigmoidf_(v);
        }
    }
    *(float4*)&out[flat] = make_float4(res[0], res[1], res[2], res[3]);
}

// ---------------------------------------------------------------------------
// sequential softmax chain: c[t][s] = 0.5 * softmax_s(lg[t] - 0.1*usage)
// ---------------------------------------------------------------------------
__global__ __launch_bounds__(256) void softmax_chain(
    const float* __restrict__ lg, float* __restrict__ cbuf) {
    const int s = threadIdx.x, lane = s & 31, wid = s >> 5;
    __shared__ float redm[8], reds[8];
    __shared__ float bmax, bsum;
    float usage = 0.f;
    for (int t = 0; t < TT; t++) {
        const float v = fmaf(-0.1f, usage, lg[t * SLOTSS + s]);
        float m = v;
#pragma unroll
        for (int o = 16; o > 0; o >>= 1) m = fmaxf(m, __shfl_xor_sync(0xffffffffu, m, o));
        if (lane == 0) redm[wid] = m;
        __syncthreads();
        if (s == 0) {
            float mm = redm[0];
#pragma unroll
            for (int i = 1; i < 8; i++) mm = fmaxf(mm, redm[i]);
            bmax = mm;
        }
        __syncthreads();
        const float e = expf(v - bmax);
        float su = e;
#pragma unroll
        for (int o = 16; o > 0; o >>= 1) su += __shfl_xor_sync(0xffffffffu, su, o);
        if (lane == 0) reds[wid] = su;
        __syncthreads();
        if (s == 0) {
            float ss = 0.f;
#pragma unroll
            for (int i = 0; i < 8; i++) ss += reds[i];
            bsum = ss;
        }
        __syncthreads();
        const float wgt = e / bsum;
        cbuf[t * SLOTSS + s] = 0.5f * wgt;
        usage += wgt;
        __syncthreads();
    }
}

// ---------------------------------------------------------------------------
// memory update recurrence over T=64 in registers
// ---------------------------------------------------------------------------
__global__ __launch_bounds__(256) void memupd_kernel(
    const float* __restrict__ cbuf, const float* __restrict__ er,
    const float* __restrict__ ad, const float* __restrict__ mem0,
    float* __restrict__ out) {
    __shared__ __align__(16) float cs[64][64];
    __shared__ __align__(16) float es[64][64];
    __shared__ __align__(16) float ds[64][64];
    const int tid = threadIdx.x;
    const int S0 = (blockIdx.x & 3) * 64;
    const int D0 = (blockIdx.x >> 2) * 64;
#pragma unroll
    for (int j = 0; j < 4; j++) {
        int f = tid + j * 256;
        int t = f >> 4, q = (f & 15) * 4;
        *(float4*)&cs[t][q] = *(const float4*)&cbuf[(size_t)t * SLOTSS + S0 + q];
        *(float4*)&es[t][q] = *(const float4*)&er[(size_t)t * DIMM + D0 + q];
        *(float4*)&ds[t][q] = *(const float4*)&ad[(size_t)t * DIMM + D0 + q];
    }
    __syncthreads();
    const int sg = (tid >> 4) * 4, dg = (tid & 15) * 4;
    float m[4][4];
#pragma unroll
    for (int j = 0; j < 4; j++)
        *(float4*)m[j] = *(const float4*)&mem0[(size_t)(S0 + sg + j) * DIMM + D0 + dg];
    for (int t = 0; t < 64; t++) {
        float4 c4 = *(const float4*)&cs[t][sg];
        float4 e4 = *(const float4*)&es[t][dg];
        float4 a4 = *(const float4*)&ds[t][dg];
        float c[4] = {c4.x, c4.y, c4.z, c4.w};
        float e[4] = {e4.x, e4.y, e4.z, e4.w};
        float a[4] = {a4.x, a4.y, a4.z, a4.w};
#pragma unroll
        for (int j = 0; j < 4; j++)
#pragma unroll
            for (int l = 0; l < 4; l++)
                m[j][l] = fmaf(c[j], fmaf(-e[l], m[j][l], a[l]), m[j][l]);
    }
#pragma unroll
    for (int j = 0; j < 4; j++)
        *(float4*)&out[(size_t)(S0 + sg + j) * DIMM + D0 + dg] = *(float4*)m[j];
}

// ---------------------------------------------------------------------------
// launch
// ---------------------------------------------------------------------------
extern "C" void kernel_launch(void* const* d_in, const int* in_sizes, int n_in,
                              void* d_out, int out_size) {
    const float* traces = (const float*)d_in[0];
    const float* noise  = (const float*)d_in[1];
    const float* mem0   = (const float*)d_in[2];
    const float* W1 = (const float*)d_in[4];
    const float* b1 = (const float*)d_in[5];
    const float* W2 = (const float*)d_in[6];
    const float* b2 = (const float*)d_in[7];
    const float* Wl = (const float*)d_in[8];
    const float* bl = (const float*)d_in[9];
    const float* vw = (const float*)d_in[10];
    const float* vb = (const float*)d_in[11];
    const float* Wg = (const float*)d_in[12];
    const float* bg = (const float*)d_in[13];
    const float* Wa = (const float*)d_in[14];
    const float* ba = (const float*)d_in[15];
    const float* We = (const float*)d_in[16];
    const float* be = (const float*)d_in[17];
    const float* Wad = (const float*)d_in[18];
    const float* bad = (const float*)d_in[19];
    const int* idx = (const int*)d_in[20];
    float* out = (float*)d_out;

    float *noisy, *h, *x, *lv, *gated, *er, *ad, *partb, *lgb, *cbuf;
    cudaGetSymbolAddress((void**)&noisy, g_noisy);
    cudaGetSymbolAddress((void**)&h, g_h);
    cudaGetSymbolAddress((void**)&x, g_x);
    cudaGetSymbolAddress((void**)&lv, g_lv);
    cudaGetSymbolAddress((void**)&gated, g_gated);
    cudaGetSymbolAddress((void**)&er, g_er);
    cudaGetSymbolAddress((void**)&ad, g_ad);
    cudaGetSymbolAddress((void**)&partb, g_part);
    cudaGetSymbolAddress((void**)&lgb, g_lg);
    cudaGetSymbolAddress((void**)&cbuf, g_c);

    prep_kernel<<<dim3(2, TT), 256>>>(traces, noise, idx, noisy);

    const dim3 gbig(DIMM / 128, KS);    // (16, 8)
    const dim3 gsm(SLOTSS / 128, KS);   // (2, 8)
    const int eb = TT * DIMM / 1024;    // 128
    const int ebs = TT * SLOTSS / 1024; // 16

    gemm_mma<<<gbig, 256>>>(noisy, W1, partb, DIMM);
    reduce_epi<M_RELU><<<eb, 256>>>(partb, b1, h, nullptr, nullptr, nullptr, DIMM);

    gemm_mma<<<gbig, 256>>>(h, W2, partb, DIMM);
    reduce_epi<M_ID><<<eb, 256>>>(partb, b2, x, nullptr, nullptr, nullptr, DIMM);

    gemm_mma<<<gbig, 256>>>(x, Wl, partb, DIMM);
    reduce_epi<M_LIG><<<eb, 256>>>(partb, bl, lv, nullptr, vw, vb, DIMM);

    gemm_mma<<<gbig, 256>>>(lv, Wg, partb, DIMM);
    reduce_epi<M_GATE><<<eb, 256>>>(partb, bg, gated, x, nullptr, nullptr, DIMM);

    gemm_mma<<<gbig, 256>>>(gated, We, partb, DIMM);
    reduce_epi<M_SIG><<<eb, 256>>>(partb, be, er, nullptr, nullptr, nullptr, DIMM);

    gemm_mma<<<gbig, 256>>>(gated, Wad, partb, DIMM);
    reduce_epi<M_ID><<<eb, 256>>>(partb, bad, ad, nullptr, nullptr, nullptr, DIMM);

    gemm_mma<<<gsm, 256>>>(gated, Wa, partb, SLOTSS);
    reduce_epi<M_ID><<<ebs, 256>>>(partb, ba, lgb, nullptr, nullptr, nullptr, SLOTSS);

    softmax_chain<<<1, 256>>>(lgb, cbuf);
    memupd_kernel<<<128, 256>>>(cbuf, er, ad, mem0, out);
}

// round 3
// speedup vs baseline: 3.6833x; 1.5137x over previous
#include <cuda_runtime.h>
#include <cuda_bf16.h>
#include <math.h>
#include <stdint.h>

#define TT 64
#define DIMM 2048
#define SLOTSS 256
#define KS 16
#define KPER (DIMM / KS)    // 128
#define NCHUNK (KPER / 16)  // 8
#define SPAD 40             // smem row stride: 32 data + 8 pad -> conflict-free ldmatrix

// -------- device scratch --------
__device__ float g_h[TT * DIMM];
__device__ float g_x[TT * DIMM];
__device__ float g_lv[TT * DIMM];
__device__ float g_gated[TT * DIMM];
__device__ float g_er[TT * DIMM];
__device__ float g_ad[TT * DIMM];
__device__ float g_partA[KS * TT * DIMM];    // 8 MB
__device__ float g_partB[KS * TT * DIMM];    // 8 MB
__device__ float g_partS[KS * TT * SLOTSS];  // 1 MB
__device__ float g_lg[TT * SLOTSS];
__device__ float g_c[TT * SLOTSS];

__device__ __forceinline__ float sigmoidf_(float v) { return 1.f / (1.f + expf(-v)); }

enum { M_RELU = 0, M_ID, M_LIG, M_GATE, M_SIG };

// ---------------------------------------------------------------------------
// Tensor-core GEMM partial: part[ks][t][n] = sum_{k in slab} A[t][k]*W[n][k]
// fp32 via bf16 hi/lo split (3 MMA passes). Block: 64x128 tile, K-slab 128,
// 256 threads (8 warps, 32x32 warp tiles). 3-stage register prefetch over
// double-buffered smem. grid = (Ntot/128, KS). PREP=1 fuses the trace gather
// + noise into the A load (first layer).
// ---------------------------------------------------------------------------
__device__ __forceinline__ void ldsm4(uint32_t* r, uint32_t addr) {
    asm volatile("ldmatrix.sync.aligned.m8n8.x4.shared.b16 {%0,%1,%2,%3}, [%4];"
                 : "=r"(r[0]), "=r"(r[1]), "=r"(r[2]), "=r"(r[3]) : "r"(addr));
}
__device__ __forceinline__ void mma16816(float* d, const uint32_t* a, uint32_t b0, uint32_t b1) {
    asm volatile(
        "mma.sync.aligned.m16n8k16.row.col.f32.bf16.bf16.f32 "
        "{%0,%1,%2,%3}, {%4,%5,%6,%7}, {%8,%9}, {%0,%1,%2,%3};"
        : "+f"(d[0]), "+f"(d[1]), "+f"(d[2]), "+f"(d[3])
        : "r"(a[0]), "r"(a[1]), "r"(a[2]), "r"(a[3]), "r"(b0), "r"(b1));
}

template <int PREP>
__global__ __launch_bounds__(256, 2) void gemm_mma(
    const float* __restrict__ A, const float* __restrict__ W,
    float* __restrict__ part, int Ntot,
    const float* __restrict__ noise, const int* __restrict__ idx) {
    __shared__ __nv_bfloat16 As[2][64][SPAD];   // cols 0..15 hi, 16..31 lo
    __shared__ __nv_bfloat16 Ws[2][128][SPAD];

    const int tid = threadIdx.x;
    const int n0 = blockIdx.x * 128;
    const int kb = blockIdx.y * KPER;

    const int a_row = tid >> 2, a_kq = (tid & 3) * 4;
    const float* Ag;
    const float* Ng = nullptr;
    if (PREP) {
        int row = __ldg(&idx[a_row]);
        Ag = A + (size_t)row * DIMM + kb + a_kq;
        Ng = noise + (size_t)a_row * DIMM + kb + a_kq;
    } else {
        Ag = A + (size_t)a_row * DIMM + kb + a_kq;
    }
    const int w_row = tid >> 1, w_kq = (tid & 1) * 8;
    const float* Wgp = W + (size_t)(n0 + w_row) * DIMM + kb + w_kq;

    const int lane = tid & 31, wid = tid >> 5;
    const int m0w = (wid >> 2) * 32;
    const int n0w = (wid & 3) * 32;
    const int g = lane >> 3, r = lane & 7;
    const int aoff = (m0w + (g & 1) * 8 + r) * SPAD + (g >> 1) * 8;
    const int boff = (n0w + (g >> 1) * 8 + r) * SPAD + (g & 1) * 8;

    const uint32_t asbase = (uint32_t)__cvta_generic_to_shared(&As[0][0][0]);
    const uint32_t wsbase = (uint32_t)__cvta_generic_to_shared(&Ws[0][0][0]);
    const uint32_t ABUF = 64 * SPAD * 2, WBUF = 128 * SPAD * 2;

    float avs[3][4], wvs[3][8];

#define LOAD_CHUNK(st, c)                                                   \
    {                                                                       \
        float4 t4 = *(const float4*)(Ag + (c) * 16);                        \
        if (PREP) {                                                         \
            float4 n4 = *(const float4*)(Ng + (c) * 16);                    \
            t4.x = fmaf(0.01f, n4.x, t4.x); t4.y = fmaf(0.01f, n4.y, t4.y); \
            t4.z = fmaf(0.01f, n4.z, t4.z); t4.w = fmaf(0.01f, n4.w, t4.w); \
        }                                                                   \
        avs[st][0] = t4.x; avs[st][1] = t4.y;                               \
        avs[st][2] = t4.z; avs[st][3] = t4.w;                               \
        float4 u0 = *(const float4*)(Wgp + (c) * 16);                       \
        float4 u1 = *(const float4*)(Wgp + (c) * 16 + 4);                   \
        wvs[st][0] = u0.x; wvs[st][1] = u0.y; wvs[st][2] = u0.z;            \
        wvs[st][3] = u0.w; wvs[st][4] = u1.x; wvs[st][5] = u1.y;            \
        wvs[st][6] = u1.z; wvs[st][7] = u1.w;                               \
    }
#define CVT_STORE(st, buf)                                                  \
    {                                                                       \
        _Pragma("unroll") for (int i = 0; i < 4; i++) {                     \
            __nv_bfloat16 hi = __float2bfloat16(avs[st][i]);                \
            float rem = avs[st][i] - __bfloat162float(hi);                  \
            As[buf][a_row][a_kq + i] = hi;                                  \
            As[buf][a_row][a_kq + i + 16] = __float2bfloat16(rem);          \
        }                                                                   \
        _Pragma("unroll") for (int i = 0; i < 8; i++) {                     \
            __nv_bfloat16 hi = __float2bfloat16(wvs[st][i]);                \
            float rem = wvs[st][i] - __bfloat162float(hi);                  \
            Ws[buf][w_row][w_kq + i] = hi;                                  \
            Ws[buf][w_row][w_kq + i + 16] = __float2bfloat16(rem);          \
        }                                                                   \
    }

    // prologue: stages 0..2 <- chunks 0..2; store chunk0 -> smem buf0
    LOAD_CHUNK(0, 0);
    LOAD_CHUNK(1, 1);
    LOAD_CHUNK(2, 2);
    CVT_STORE(0, 0);
    __syncthreads();

    float d[2][4][4];
#pragma unroll
    for (int mt = 0; mt < 2; mt++)
#pragma unroll
        for (int nf = 0; nf < 4; nf++)
#pragma unroll
            for (int j = 0; j < 4; j++) d[mt][nf][j] = 0.f;

#pragma unroll
    for (int c = 0; c < NCHUNK; c++) {
        const int cur = c & 1;
        if (c + 3 < NCHUNK) LOAD_CHUNK(c % 3, c + 3);

        uint32_t a[2][2][4], b[2][2][4];
#pragma unroll
        for (int mt = 0; mt < 2; mt++)
#pragma unroll
            for (int sec = 0; sec < 2; sec++)
                ldsm4(a[mt][sec], asbase + cur * ABUF + (uint32_t)(aoff + mt * 16 * SPAD + sec * 16) * 2);
#pragma unroll
        for (int pr = 0; pr < 2; pr++)
#pragma unroll
            for (int sec = 0; sec < 2; sec++)
                ldsm4(b[pr][sec], wsbase + cur * WBUF + (uint32_t)(boff + pr * 16 * SPAD + sec * 16) * 2);
#pragma unroll
        for (int q = 0; q < 3; q++) {
            const int as = (q == 2) ? 1 : 0;
            const int ws = (q == 1) ? 1 : 0;
#pragma unroll
            for (int mt = 0; mt < 2; mt++)
#pragma unroll
                for (int nf = 0; nf < 4; nf++) {
                    const int pr = nf >> 1, hl = nf & 1;
                    mma16816(d[mt][nf], a[mt][as], b[pr][ws][hl * 2], b[pr][ws][hl * 2 + 1]);
                }
        }
        if (c + 1 < NCHUNK) CVT_STORE((c + 1) % 3, cur ^ 1);
        __syncthreads();
    }
#undef LOAD_CHUNK
#undef CVT_STORE

    const int mbase = blockIdx.y * 64;
#pragma unroll
    for (int mt = 0; mt < 2; mt++)
#pragma unroll
        for (int nf = 0; nf < 4; nf++) {
            const int m = m0w + mt * 16 + (lane >> 2);
            const int n = n0 + n0w + nf * 8 + (lane & 3) * 2;
            *(float2*)&part[(size_t)(mbase + m) * Ntot + n] = make_float2(d[mt][nf][0], d[mt][nf][1]);
            *(float2*)&part[(size_t)(mbase + m + 8) * Ntot + n] = make_float2(d[mt][nf][2], d[mt][nf][3]);
        }
}

// ---------------------------------------------------------------------------
// reduce k-split partials + bias + activation (one tensor)
// ---------------------------------------------------------------------------
template <int MODE>
__global__ __launch_bounds__(256) void reduce_epi(
    const float* __restrict__ part, const float* __restrict__ bias,
    float* __restrict__ out, const float* __restrict__ xbuf,
    const float* __restrict__ vw, const float* __restrict__ vb) {
    const int flat = (blockIdx.x * 256 + threadIdx.x) * 4;
    const int t = flat / DIMM;
    const int n = flat % DIMM;
    float acc[4] = {0.f, 0.f, 0.f, 0.f};
#pragma unroll
    for (int k = 0; k < KS; k++) {
        float4 p = *(const float4*)&part[(size_t)k * TT * DIMM + flat];
        acc[0] += p.x; acc[1] += p.y; acc[2] += p.z; acc[3] += p.w;
    }
    float4 b4 = *(const float4*)&bias[n];
    float bb[4] = {b4.x, b4.y, b4.z, b4.w};
    float res[4];
#pragma unroll
    for (int j = 0; j < 4; j++) {
        const float v = acc[j] + bb[j];
        if (MODE == M_RELU) {
            res[j] = v > 0.f ? v : 0.f;
        } else if (MODE == M_ID) {
            res[j] = v;
        } else if (MODE == M_LIG) {
            float ang = fmodf(0.37699111843077515f * (float)(t + 1), 6.2831853071795865f);
            float ps = -cosf(ang);
            float volt = sigmoidf_(fmaf(ps, vw[n + j], vb[n + j]));
            res[j] = sigmoidf_(v) * volt;
        } else {  // M_GATE
            res[j] = xbuf[flat + j] * sigmoidf_(v);
        }
    }
    *(float4*)&out[flat] = make_float4(res[0], res[1], res[2], res[3]);
}

// ---------------------------------------------------------------------------
// fused tail epilogue: er = sigmoid(redA+be), ad = redB+bad, lg = redS+ba
// blocks 0..127: er+ad (64x2048, 4/thr). blocks 128..143: lg (64x256, 4/thr).
// ---------------------------------------------------------------------------
__global__ __launch_bounds__(256) void epi_tail(
    const float* __restrict__ partA, const float* __restrict__ be,
    const float* __restrict__ partB, const float* __restrict__ bad,
    const float* __restrict__ partS, const float* __restrict__ ba,
    float* __restrict__ er, float* __restrict__ ad, float* __restrict__ lg) {
    const int b = blockIdx.x;
    if (b < 128) {
        const int flat = (b * 256 + threadIdx.x) * 4;
        const int n = flat % DIMM;
        float aA[4] = {0, 0, 0, 0}, aB[4] = {0, 0, 0, 0};
#pragma unroll
        for (int k = 0; k < KS; k++) {
            float4 p = *(const float4*)&partA[(size_t)k * TT * DIMM + flat];
            aA[0] += p.x; aA[1] += p.y; aA[2] += p.z; aA[3] += p.w;
            float4 q = *(const float4*)&partB[(size_t)k * TT * DIMM + flat];
            aB[0] += q.x; aB[1] += q.y; aB[2] += q.z; aB[3] += q.w;
        }
        float4 e4 = *(const float4*)&be[n];
        float4 d4 = *(const float4*)&bad[n];
        float eb[4] = {e4.x, e4.y, e4.z, e4.w};
        float db[4] = {d4.x, d4.y, d4.z, d4.w};
        float ro[4], ao[4];
#pragma unroll
        for (int j = 0; j < 4; j++) {
            ro[j] = sigmoidf_(aA[j] + eb[j]);
            ao[j] = aB[j] + db[j];
        }
        *(float4*)&er[flat] = make_float4(ro[0], ro[1], ro[2], ro[3]);
        *(float4*)&ad[flat] = make_float4(ao[0], ao[1], ao[2], ao[3]);
    } else {
        const int flat = ((b - 128) * 256 + threadIdx.x) * 4;
        const int n = flat % SLOTSS;
        float aS[4] = {0, 0, 0, 0};
#pragma unroll
        for (int k = 0; k < KS; k++) {
            float4 p = *(const float4*)&partS[(size_t)k * TT * SLOTSS + flat];
            aS[0] += p.x; aS[1] += p.y; aS[2] += p.z; aS[3] += p.w;
        }
        float4 b4 = *(const float4*)&ba[n];
        *(float4*)&lg[flat] = make_float4(aS[0] + b4.x, aS[1] + b4.y, aS[2] + b4.z, aS[3] + b4.w);
    }
}

// ---------------------------------------------------------------------------
// softmax chain: rowmax in parallel, then 64-step chain with sum-only
// reduction, one __syncthreads per step (double-buffered partials).
// ---------------------------------------------------------------------------
__global__ __launch_bounds__(256) void softmax_chain(
    const float* __restrict__ lg, float* __restrict__ cbuf) {
    const int s = threadIdx.x, lane = s & 31, wid = s >> 5;
    __shared__ float rowmax[64];
    __shared__ float psum[2][8];

    // phase 1: per-row max (warp w handles rows 8w..8w+7)
#pragma unroll
    for (int r = 0; r < 8; r++) {
        const int row = wid * 8 + r;
        float m = -1e30f;
#pragma unroll
        for (int j = 0; j < 8; j++) m = fmaxf(m, lg[row * SLOTSS + j * 32 + lane]);
#pragma unroll
        for (int o = 16; o > 0; o >>= 1) m = fmaxf(m, __shfl_xor_sync(0xffffffffu, m, o));
        if (lane == 0) rowmax[row] = m;
    }
    __syncthreads();

    // phase 2: sequential chain
    float usage = 0.f;
    for (int t = 0; t < TT; t++) {
        const float v = lg[t * SLOTSS + s] - 0.1f * usage - rowmax[t];
        const float e = expf(v);   // v <= 0, safe
        float su = e;
#pragma unroll
        for (int o = 16; o > 0; o >>= 1) su += __shfl_xor_sync(0xffffffffu, su, o);
        if (lane == 0) psum[t & 1][wid] = su;
        __syncthreads();
        float tot = 0.f;
#pragma unroll
        for (int i = 0; i < 8; i++) tot += psum[t & 1][i];
        const float wgt = e / tot;
        cbuf[t * SLOTSS + s] = 0.5f * wgt;
        usage += wgt;
    }
}

// ---------------------------------------------------------------------------
// memory update recurrence over T=64 in registers
// ---------------------------------------------------------------------------
__global__ __launch_bounds__(256) void memupd_kernel(
    const float* __restrict__ cbuf, const float* __restrict__ er,
    const float* __restrict__ ad, const float* __restrict__ mem0,
    float* __restrict__ out) {
    __shared__ __align__(16) float cs[64][64];
    __shared__ __align__(16) float es[64][64];
    __shared__ __align__(16) float ds[64][64];
    const int tid = threadIdx.x;
    const int S0 = (blockIdx.x & 3) * 64;
    const int D0 = (blockIdx.x >> 2) * 64;
#pragma unroll
    for (int j = 0; j < 4; j++) {
        int f = tid + j * 256;
        int t = f >> 4, q = (f & 15) * 4;
        *(float4*)&cs[t][q] = *(const float4*)&cbuf[(size_t)t * SLOTSS + S0 + q];
        *(float4*)&es[t][q] = *(const float4*)&er[(size_t)t * DIMM + D0 + q];
        *(float4*)&ds[t][q] = *(const float4*)&ad[(size_t)t * DIMM + D0 + q];
    }
    __syncthreads();
    const int sg = (tid >> 4) * 4, dg = (tid & 15) * 4;
    float m[4][4];
#pragma unroll
    for (int j = 0; j < 4; j++)
        *(float4*)m[j] = *(const float4*)&mem0[(size_t)(S0 + sg + j) * DIMM + D0 + dg];
    for (int t = 0; t < 64; t++) {
        float4 c4 = *(const float4*)&cs[t][sg];
        float4 e4 = *(const float4*)&es[t][dg];
        float4 a4 = *(const float4*)&ds[t][dg];
        float c[4] = {c4.x, c4.y, c4.z, c4.w};
        float e[4] = {e4.x, e4.y, e4.z, e4.w};
        float a[4] = {a4.x, a4.y, a4.z, a4.w};
#pragma unroll
        for (int j = 0; j < 4; j++)
#pragma unroll
            for (int l = 0; l < 4; l++)
                m[j][l] = fmaf(c[j], fmaf(-e[l], m[j][l], a[l]), m[j][l]);
    }
#pragma unroll
    for (int j = 0; j < 4; j++)
        *(float4*)&out[(size_t)(S0 + sg + j) * DIMM + D0 + dg] = *(float4*)m[j];
}

// ---------------------------------------------------------------------------
// launch
// ---------------------------------------------------------------------------
extern "C" void kernel_launch(void* const* d_in, const int* in_sizes, int n_in,
                              void* d_out, int out_size) {
    const float* traces = (const float*)d_in[0];
    const float* noise  = (const float*)d_in[1];
    const float* mem0   = (const float*)d_in[2];
    const float* W1 = (const float*)d_in[4];
    const float* b1 = (const float*)d_in[5];
    const float* W2 = (const float*)d_in[6];
    const float* b2 = (const float*)d_in[7];
    const float* Wl = (const float*)d_in[8];
    const float* bl = (const float*)d_in[9];
    const float* vw = (const float*)d_in[10];
    const float* vb = (const float*)d_in[11];
    const float* Wg = (const float*)d_in[12];
    const float* bg = (const float*)d_in[13];
    const float* Wa = (const float*)d_in[14];
    const float* ba = (const float*)d_in[15];
    const float* We = (const float*)d_in[16];
    const float* be = (const float*)d_in[17];
    const float* Wad = (const float*)d_in[18];
    const float* bad = (const float*)d_in[19];
    const int* idx = (const int*)d_in[20];
    float* out = (float*)d_out;

    float *h, *x, *lv, *gated, *er, *ad, *pA, *pB, *pS, *lgb, *cbuf;
    cudaGetSymbolAddress((void**)&h, g_h);
    cudaGetSymbolAddress((void**)&x, g_x);
    cudaGetSymbolAddress((void**)&lv, g_lv);
    cudaGetSymbolAddress((void**)&gated, g_gated);
    cudaGetSymbolAddress((void**)&er, g_er);
    cudaGetSymbolAddress((void**)&ad, g_ad);
    cudaGetSymbolAddress((void**)&pA, g_partA);
    cudaGetSymbolAddress((void**)&pB, g_partB);
    cudaGetSymbolAddress((void**)&pS, g_partS);
    cudaGetSymbolAddress((void**)&lgb, g_lg);
    cudaGetSymbolAddress((void**)&cbuf, g_c);

    const dim3 gbig(DIMM / 128, KS);   // (16,16) = 256 blocks
    const dim3 gsm(SLOTSS / 128, KS);  // (2,16)
    const int eb = TT * DIMM / 1024;   // 128

    gemm_mma<1><<<gbig, 256>>>(traces, W1, pA, DIMM, noise, idx);
    reduce_epi<M_RELU><<<eb, 256>>>(pA, b1, h, nullptr, nullptr, nullptr);

    gemm_mma<0><<<gbig, 256>>>(h, W2, pA, DIMM, nullptr, nullptr);
    reduce_epi<M_ID><<<eb, 256>>>(pA, b2, x, nullptr, nullptr, nullptr);

    gemm_mma<0><<<gbig, 256>>>(x, Wl, pA, DIMM, nullptr, nullptr);
    reduce_epi<M_LIG><<<eb, 256>>>(pA, bl, lv, nullptr, vw, vb);

    gemm_mma<0><<<gbig, 256>>>(lv, Wg, pA, DIMM, nullptr, nullptr);
    reduce_epi<M_GATE><<<eb, 256>>>(pA, bg, gated, x, nullptr, nullptr);

    gemm_mma<0><<<gbig, 256>>>(gated, We, pA, DIMM, nullptr, nullptr);
    gemm_mma<0><<<gbig, 256>>>(gated, Wad, pB, DIMM, nullptr, nullptr);
    gemm_mma<0><<<gsm, 256>>>(gated, Wa, pS, SLOTSS, nullptr, nullptr);
    epi_tail<<<144, 256>>>(pA, be, pB, bad, pS, ba, er, ad, lgb);

    softmax_chain<<<1, 256>>>(lgb, cbuf);
    memupd_kernel<<<128, 256>>>(cbuf, er, ad, mem0, out);
}

// round 4
// speedup vs baseline: 3.7961x; 1.0306x over previous
#include <cuda_runtime.h>
#include <cuda_bf16.h>
#include <math.h>
#include <stdint.h>

#define TT 64
#define DIMM 2048
#define SLOTSS 256
#define KS 16
#define KPER (DIMM / KS)    // 128
#define NCHUNK (KPER / 16)  // 8
#define SPAD 40
#define NB 256

// -------- device scratch --------
__device__ float g_h[TT * DIMM];
__device__ float g_x[TT * DIMM];
__device__ float g_lv[TT * DIMM];
__device__ float g_gated[TT * DIMM];
__device__ float g_er[TT * DIMM];
__device__ float g_ad[TT * DIMM];
__device__ float g_pA[KS * TT * DIMM];
__device__ float g_pB[KS * TT * DIMM];
__device__ float g_pS[KS * TT * SLOTSS];
__device__ float g_lg[TT * SLOTSS];
__device__ float g_c[TT * SLOTSS];
__device__ unsigned g_count = 0;
__device__ unsigned g_gen = 0;

__device__ __forceinline__ float sigmoidf_(float v) { return 1.f / (1.f + expf(-v)); }

enum { M_RELU = 0, M_ID, M_LIG, M_GATE };

// -------- shared memory union across phases --------
struct SmemG { __nv_bfloat16 As[2][64][SPAD]; __nv_bfloat16 Ws[2][128][SPAD]; };  // 30720 B
struct SmemM { float cs[64][32]; float es[64][64]; float ds[64][64]; };           // 40960 B
struct SmemS { float rowmax[64]; float psum[2][8]; };
union SmemU { SmemG g; SmemM m; SmemS s; };

// -------- software grid barrier (all NB blocks resident by construction) ----
__device__ __forceinline__ void gridbar() {
    __threadfence();          // my stores visible device-wide
    __syncthreads();          // whole block's fences done
    if (threadIdx.x == 0) {
        unsigned gen = *(volatile unsigned*)&g_gen;
        unsigned prev = atomicAdd(&g_count, 1);
        if (prev == NB - 1) {
            g_count = 0;
            __threadfence();
            *(volatile unsigned*)&g_gen = gen + 1;
        } else {
            while (*(volatile unsigned*)&g_gen == gen) { __nanosleep(32); }
        }
        __threadfence();
    }
    __syncthreads();
}

// -------- tensor-core GEMM phase (same core as R3, inline A-cg loads) -------
__device__ __forceinline__ void ldsm4(uint32_t* r, uint32_t addr) {
    asm volatile("ldmatrix.sync.aligned.m8n8.x4.shared.b16 {%0,%1,%2,%3}, [%4];"
                 : "=r"(r[0]), "=r"(r[1]), "=r"(r[2]), "=r"(r[3]) : "r"(addr));
}
__device__ __forceinline__ void mma16816(float* d, const uint32_t* a, uint32_t b0, uint32_t b1) {
    asm volatile(
        "mma.sync.aligned.m16n8k16.row.col.f32.bf16.bf16.f32 "
        "{%0,%1,%2,%3}, {%4,%5,%6,%7}, {%8,%9}, {%0,%1,%2,%3};"
        : "+f"(d[0]), "+f"(d[1]), "+f"(d[2]), "+f"(d[3])
        : "r"(a[0]), "r"(a[1]), "r"(a[2]), "r"(a[3]), "r"(b0), "r"(b1));
}

template <int PREP, int ACG>
__device__ void gemm_phase(SmemU* sm, const float* __restrict__ A,
                           const float* __restrict__ W, float* __restrict__ part,
                           int Ntot, int nblk,
                           const float* __restrict__ noise, const int* __restrict__ idx) {
    const int bid = blockIdx.x;
    const int tid = threadIdx.x;
    const int n0 = (bid % nblk) * 128;
    const int kb = (bid / nblk) * KPER;

    const int a_row = tid >> 2, a_kq = (tid & 3) * 4;
    const float* Ag;
    const float* Ng = nullptr;
    if (PREP) {
        int row = __ldg(&idx[a_row]);
        Ag = A + (size_t)row * DIMM + kb + a_kq;
        Ng = noise + (size_t)a_row * DIMM + kb + a_kq;
    } else {
        Ag = A + (size_t)a_row * DIMM + kb + a_kq;
    }
    const int w_row = tid >> 1, w_kq = (tid & 1) * 8;
    const float* Wgp = W + (size_t)(n0 + w_row) * DIMM + kb + w_kq;

    const int lane = tid & 31, wid = tid >> 5;
    const int m0w = (wid >> 2) * 32;
    const int n0w = (wid & 3) * 32;
    const int gq = lane >> 3, rq = lane & 7;
    const int aoff = (m0w + (gq & 1) * 8 + rq) * SPAD + (gq >> 1) * 8;
    const int boff = (n0w + (gq >> 1) * 8 + rq) * SPAD + (gq & 1) * 8;

    const uint32_t asbase = (uint32_t)__cvta_generic_to_shared(&sm->g.As[0][0][0]);
    const uint32_t wsbase = (uint32_t)__cvta_generic_to_shared(&sm->g.Ws[0][0][0]);
    const uint32_t ABUF = 64 * SPAD * 2, WBUF = 128 * SPAD * 2;

    float avs[3][4], wvs[3][8];

#define LOAD_CHUNK(st, c)                                                    \
    {                                                                        \
        float4 t4 = ACG ? __ldcg((const float4*)(Ag + (c) * 16))             \
                        : __ldg((const float4*)(Ag + (c) * 16));             \
        if (PREP) {                                                          \
            float4 n4 = __ldg((const float4*)(Ng + (c) * 16));               \
            t4.x = fmaf(0.01f, n4.x, t4.x); t4.y = fmaf(0.01f, n4.y, t4.y);  \
            t4.z = fmaf(0.01f, n4.z, t4.z); t4.w = fmaf(0.01f, n4.w, t4.w);  \
        }                                                                    \
        avs[st][0] = t4.x; avs[st][1] = t4.y;                                \
        avs[st][2] = t4.z; avs[st][3] = t4.w;                                \
        float4 u0 = __ldg((const float4*)(Wgp + (c) * 16));                  \
        float4 u1 = __ldg((const float4*)(Wgp + (c) * 16 + 4));              \
        wvs[st][0] = u0.x; wvs[st][1] = u0.y; wvs[st][2] = u0.z;             \
        wvs[st][3] = u0.w; wvs[st][4] = u1.x; wvs[st][5] = u1.y;             \
        wvs[st][6] = u1.z; wvs[st][7] = u1.w;                                \
    }
#define CVT_STORE(st, buf)                                                   \
    {                                                                        \
        _Pragma("unroll") for (int i = 0; i < 4; i++) {                      \
            __nv_bfloat16 hi = __float2bfloat16(avs[st][i]);                 \
            float rem = avs[st][i] - __bfloat162float(hi);                   \
            sm->g.As[buf][a_row][a_kq + i] = hi;                             \
            sm->g.As[buf][a_row][a_kq + i + 16] = __float2bfloat16(rem);     \
        }                                                                    \
        _Pragma("unroll") for (int i = 0; i < 8; i++) {                      \
            __nv_bfloat16 hi = __float2bfloat16(wvs[st][i]);                 \
            float rem = wvs[st][i] - __bfloat162float(hi);                   \
            sm->g.Ws[buf][w_row][w_kq + i] = hi;                             \
            sm->g.Ws[buf][w_row][w_kq + i + 16] = __float2bfloat16(rem);     \
        }                                                                    \
    }

    LOAD_CHUNK(0, 0);
    LOAD_CHUNK(1, 1);
    LOAD_CHUNK(2, 2);
    CVT_STORE(0, 0);
    __syncthreads();

    float d[2][4][4];
#pragma unroll
    for (int mt = 0; mt < 2; mt++)
#pragma unroll
        for (int nf = 0; nf < 4; nf++)
#pragma unroll
            for (int j = 0; j < 4; j++) d[mt][nf][j] = 0.f;

#pragma unroll
    for (int c = 0; c < NCHUNK; c++) {
        const int cur = c & 1;
        if (c + 3 < NCHUNK) LOAD_CHUNK(c % 3, c + 3);

        uint32_t a[2][2][4], b[2][2][4];
#pragma unroll
        for (int mt = 0; mt < 2; mt++)
#pragma unroll
            for (int sec = 0; sec < 2; sec++)
                ldsm4(a[mt][sec], asbase + cur * ABUF + (uint32_t)(aoff + mt * 16 * SPAD + sec * 16) * 2);
#pragma unroll
        for (int pr = 0; pr < 2; pr++)
#pragma unroll
            for (int sec = 0; sec < 2; sec++)
                ldsm4(b[pr][sec], wsbase + cur * WBUF + (uint32_t)(boff + pr * 16 * SPAD + sec * 16) * 2);
#pragma unroll
        for (int q = 0; q < 3; q++) {
            const int as = (q == 2) ? 1 : 0;
            const int ws = (q == 1) ? 1 : 0;
#pragma unroll
            for (int mt = 0; mt < 2; mt++)
#pragma unroll
                for (int nf = 0; nf < 4; nf++) {
                    const int pr = nf >> 1, hl = nf & 1;
                    mma16816(d[mt][nf], a[mt][as], b[pr][ws][hl * 2], b[pr][ws][hl * 2 + 1]);
                }
        }
        if (c + 1 < NCHUNK) CVT_STORE((c + 1) % 3, cur ^ 1);
        __syncthreads();
    }
#undef LOAD_CHUNK
#undef CVT_STORE

    const int mbase = (bid / nblk) * 64;
#pragma unroll
    for (int mt = 0; mt < 2; mt++)
#pragma unroll
        for (int nf = 0; nf < 4; nf++) {
            const int m = m0w + mt * 16 + (lane >> 2);
            const int n = n0 + n0w + nf * 8 + (lane & 3) * 2;
            *(float2*)&part[(size_t)(mbase + m) * Ntot + n] = make_float2(d[mt][nf][0], d[mt][nf][1]);
            *(float2*)&part[(size_t)(mbase + m + 8) * Ntot + n] = make_float2(d[mt][nf][2], d[mt][nf][3]);
        }
}

// -------- inline reduce + activation (64x2048 = 32768 float4) --------------
template <int MODE>
__device__ void reduce_phase(const float* __restrict__ part, const float* __restrict__ bias,
                             float* __restrict__ out, const float* __restrict__ xbuf,
                             const float* __restrict__ vw, const float* __restrict__ vb) {
    if (threadIdx.x >= 128) return;
    const int f4 = blockIdx.x * 128 + threadIdx.x;  // 0..32767
    const int flat = f4 * 4;
    const int t = flat / DIMM;
    const int n = flat % DIMM;
    float acc[4] = {0.f, 0.f, 0.f, 0.f};
#pragma unroll
    for (int k = 0; k < KS; k++) {
        float4 p = __ldcg((const float4*)&part[(size_t)k * TT * DIMM + flat]);
        acc[0] += p.x; acc[1] += p.y; acc[2] += p.z; acc[3] += p.w;
    }
    float4 b4 = __ldg((const float4*)&bias[n]);
    float bb[4] = {b4.x, b4.y, b4.z, b4.w};
    float res[4];
    float4 xv;
    if (MODE == M_GATE) xv = __ldcg((const float4*)&xbuf[flat]);
    const float* xp = (const float*)&xv;
#pragma unroll
    for (int j = 0; j < 4; j++) {
        const float v = acc[j] + bb[j];
        if (MODE == M_RELU) {
            res[j] = v > 0.f ? v : 0.f;
        } else if (MODE == M_ID) {
            res[j] = v;
        } else if (MODE == M_LIG) {
            float ang = fmodf(0.37699111843077515f * (float)(t + 1), 6.2831853071795865f);
            float ps = -cosf(ang);
            float volt = sigmoidf_(fmaf(ps, __ldg(&vw[n + j]), __ldg(&vb[n + j])));
            res[j] = sigmoidf_(v) * volt;
        } else {  // M_GATE
            res[j] = xp[j] * sigmoidf_(v);
        }
    }
    *(float4*)&out[flat] = make_float4(res[0], res[1], res[2], res[3]);
}

// -------- fused tail reduce: er, ad, lg -------------------------------------
__device__ void tail_phase(const float* __restrict__ pA, const float* __restrict__ be,
                           const float* __restrict__ pB, const float* __restrict__ bad,
                           const float* __restrict__ pS, const float* __restrict__ ba,
                           float* __restrict__ er, float* __restrict__ ad,
                           float* __restrict__ lg) {
    const int gid = blockIdx.x * 256 + threadIdx.x;  // 0..65535
    if (gid < 32768) {
        const int flat = gid * 4;
        const int n = flat % DIMM;
        float aA[4] = {0, 0, 0, 0}, aB[4] = {0, 0, 0, 0};
#pragma unroll
        for (int k = 0; k < KS; k++) {
            float4 p = __ldcg((const float4*)&pA[(size_t)k * TT * DIMM + flat]);
            aA[0] += p.x; aA[1] += p.y; aA[2] += p.z; aA[3] += p.w;
            float4 q = __ldcg((const float4*)&pB[(size_t)k * TT * DIMM + flat]);
            aB[0] += q.x; aB[1] += q.y; aB[2] += q.z; aB[3] += q.w;
        }
        float4 e4 = __ldg((const float4*)&be[n]);
        float4 d4 = __ldg((const float4*)&bad[n]);
        float ro[4], ao[4];
        const float* ep = (const float*)&e4;
        const float* dp = (const float*)&d4;
#pragma unroll
        for (int j = 0; j < 4; j++) {
            ro[j] = sigmoidf_(aA[j] + ep[j]);
            ao[j] = aB[j] + dp[j];
        }
        *(float4*)&er[flat] = make_float4(ro[0], ro[1], ro[2], ro[3]);
        *(float4*)&ad[flat] = make_float4(ao[0], ao[1], ao[2], ao[3]);
    } else if (gid < 32768 + 4096) {
        const int flat = (gid - 32768) * 4;
        const int n = flat % SLOTSS;
        float aS[4] = {0, 0, 0, 0};
#pragma unroll
        for (int k = 0; k < KS; k++) {
            float4 p = __ldcg((const float4*)&pS[(size_t)k * TT * SLOTSS + flat]);
            aS[0] += p.x; aS[1] += p.y; aS[2] += p.z; aS[3] += p.w;
        }
        float4 b4 = __ldg((const float4*)&ba[n]);
        *(float4*)&lg[flat] = make_float4(aS[0] + b4.x, aS[1] + b4.y, aS[2] + b4.z, aS[3] + b4.w);
    }
}

// -------- softmax chain (block 0 only) ---------------------------------------
__device__ void softmax_phase(SmemU* sm, const float* __restrict__ lg,
                              float* __restrict__ cbuf) {
    const int s = threadIdx.x, lane = s & 31, wid = s >> 5;
    __syncthreads();
#pragma unroll
    for (int r = 0; r < 8; r++) {
        const int row = wid * 8 + r;
        float m = -1e30f;
#pragma unroll
        for (int j = 0; j < 8; j++) m = fmaxf(m, __ldcg(&lg[row * SLOTSS + j * 32 + lane]));
#pragma unroll
        for (int o = 16; o > 0; o >>= 1) m = fmaxf(m, __shfl_xor_sync(0xffffffffu, m, o));
        if (lane == 0) sm->s.rowmax[row] = m;
    }
    __syncthreads();

    float usage = 0.f;
    for (int t = 0; t < TT; t++) {
        const float v = __ldcg(&lg[t * SLOTSS + s]) - 0.1f * usage - sm->s.rowmax[t];
        const float e = expf(v);
        float su = e;
#pragma unroll
        for (int o = 16; o > 0; o >>= 1) su += __shfl_xor_sync(0xffffffffu, su, o);
        if (lane == 0) sm->s.psum[t & 1][wid] = su;
        __syncthreads();
        float tot = 0.f;
#pragma unroll
        for (int i = 0; i < 8; i++) tot += sm->s.psum[t & 1][i];
        const float wgt = e / tot;
        cbuf[t * SLOTSS + s] = 0.5f * wgt;
        usage += wgt;
    }
}

// -------- memory-update recurrence (tile 32 slots x 64 dims) -----------------
__device__ void memupd_phase(SmemU* sm, const float* __restrict__ cbuf,
                             const float* __restrict__ er, const float* __restrict__ ad,
                             const float* __restrict__ mem0, float* __restrict__ out) {
    const int tid = threadIdx.x;
    const int S0 = (blockIdx.x & 7) * 32;
    const int D0 = (blockIdx.x >> 3) * 64;
#pragma unroll
    for (int j = 0; j < 2; j++) {
        int f = tid + j * 256;
        int t = f >> 3, q = (f & 7) * 4;
        *(float4*)&sm->m.cs[t][q] = __ldcg((const float4*)&cbuf[(size_t)t * SLOTSS + S0 + q]);
    }
#pragma unroll
    for (int j = 0; j < 4; j++) {
        int f = tid + j * 256;
        int t = f >> 4, q = (f & 15) * 4;
        *(float4*)&sm->m.es[t][q] = __ldcg((const float4*)&er[(size_t)t * DIMM + D0 + q]);
        *(float4*)&sm->m.ds[t][q] = __ldcg((const float4*)&ad[(size_t)t * DIMM + D0 + q]);
    }
    __syncthreads();
    const int sg = (tid >> 4) * 2, dg = (tid & 15) * 4;
    float m[2][4];
#pragma unroll
    for (int j = 0; j < 2; j++)
        *(float4*)m[j] = __ldg((const float4*)&mem0[(size_t)(S0 + sg + j) * DIMM + D0 + dg]);
    for (int t = 0; t < 64; t++) {
        float c0 = sm->m.cs[t][sg], c1 = sm->m.cs[t][sg + 1];
        float4 e4 = *(const float4*)&sm->m.es[t][dg];
        float4 a4 = *(const float4*)&sm->m.ds[t][dg];
        float e[4] = {e4.x, e4.y, e4.z, e4.w};
        float a[4] = {a4.x, a4.y, a4.z, a4.w};
#pragma unroll
        for (int l = 0; l < 4; l++) {
            m[0][l] = fmaf(c0, fmaf(-e[l], m[0][l], a[l]), m[0][l]);
            m[1][l] = fmaf(c1, fmaf(-e[l], m[1][l], a[l]), m[1][l]);
        }
    }
#pragma unroll
    for (int j = 0; j < 2; j++)
        *(float4*)&out[(size_t)(S0 + sg + j) * DIMM + D0 + dg] = *(float4*)m[j];
}

// -------- mega kernel --------------------------------------------------------
__global__ __launch_bounds__(256, 2) void mega_kernel(
    const float* __restrict__ traces, const float* __restrict__ noise,
    const float* __restrict__ mem0,
    const float* __restrict__ W1, const float* __restrict__ b1,
    const float* __restrict__ W2, const float* __restrict__ b2,
    const float* __restrict__ Wl, const float* __restrict__ bl,
    const float* __restrict__ vw, const float* __restrict__ vb,
    const float* __restrict__ Wg, const float* __restrict__ bg,
    const float* __restrict__ Wa, const float* __restrict__ ba,
    const float* __restrict__ We, const float* __restrict__ be,
    const float* __restrict__ Wad, const float* __restrict__ bad,
    const int* __restrict__ idx, float* __restrict__ out) {
    __shared__ SmemU sm;

    gemm_phase<1, 0>(&sm, traces, W1, g_pA, DIMM, 16, noise, idx);
    gridbar();
    reduce_phase<M_RELU>(g_pA, b1, g_h, nullptr, nullptr, nullptr);
    gridbar();

    gemm_phase<0, 1>(&sm, g_h, W2, g_pA, DIMM, 16, nullptr, nullptr);
    gridbar();
    reduce_phase<M_ID>(g_pA, b2, g_x, nullptr, nullptr, nullptr);
    gridbar();

    gemm_phase<0, 1>(&sm, g_x, Wl, g_pA, DIMM, 16, nullptr, nullptr);
    gridbar();
    reduce_phase<M_LIG>(g_pA, bl, g_lv, nullptr, vw, vb);
    gridbar();

    gemm_phase<0, 1>(&sm, g_lv, Wg, g_pA, DIMM, 16, nullptr, nullptr);
    gridbar();
    reduce_phase<M_GATE>(g_pA, bg, g_gated, g_x, nullptr, nullptr);
    gridbar();

    // tri-GEMM phase: We, Wad (all blocks) + Wa (blocks 0..31)
    gemm_phase<0, 1>(&sm, g_gated, We, g_pA, DIMM, 16, nullptr, nullptr);
    __syncthreads();
    gemm_phase<0, 1>(&sm, g_gated, Wad, g_pB, DIMM, 16, nullptr, nullptr);
    if (blockIdx.x < 32) {
        __syncthreads();
        gemm_phase<0, 1>(&sm, g_gated, Wa, g_pS, SLOTSS, 2, nullptr, nullptr);
    }
    gridbar();

    tail_phase(g_pA, be, g_pB, bad, g_pS, ba, g_er, g_ad, g_lg);
    gridbar();

    if (blockIdx.x == 0) softmax_phase(&sm, g_lg, g_c);
    gridbar();

    memupd_phase(&sm, g_c, g_er, g_ad, mem0, out);
}

// ---------------------------------------------------------------------------
extern "C" void kernel_launch(void* const* d_in, const int* in_sizes, int n_in,
                              void* d_out, int out_size) {
    const float* traces = (const float*)d_in[0];
    const float* noise  = (const float*)d_in[1];
    const float* mem0   = (const float*)d_in[2];
    const float* W1 = (const float*)d_in[4];
    const float* b1 = (const float*)d_in[5];
    const float* W2 = (const float*)d_in[6];
    const float* b2 = (const float*)d_in[7];
    const float* Wl = (const float*)d_in[8];
    const float* bl = (const float*)d_in[9];
    const float* vw = (const float*)d_in[10];
    const float* vb = (const float*)d_in[11];
    const float* Wg = (const float*)d_in[12];
    const float* bg = (const float*)d_in[13];
    const float* Wa = (const float*)d_in[14];
    const float* ba = (const float*)d_in[15];
    const float* We = (const float*)d_in[16];
    const float* be = (const float*)d_in[17];
    const float* Wad = (const float*)d_in[18];
    const float* bad = (const float*)d_in[19];
    const int* idx = (const int*)d_in[20];
    float* out = (float*)d_out;

    mega_kernel<<<NB, 256>>>(traces, noise, mem0, W1, b1, W2, b2, Wl, bl, vw, vb,
                             Wg, bg, Wa, ba, We, be, Wad, bad, idx, out);
}